// round 16
// baseline (speedup 1.0000x reference)
#include <cuda_runtime.h>
#include <cuda_fp16.h>
#include <math.h>
#include <stdint.h>

#define TOPN 1000
#define BBOX_CLAMP 4.135166556742356f
#define LOSCALE 2048.0f
#define INVLOSCALE (1.0f/2048.0f)
typedef unsigned short u16;

// ---------------- scratch (device globals) ----------------
__device__ float g_c0[64*256*256];
__device__ float g_pool[64*128*128];
__device__ float g_c1[128*64*64];
__device__ float g_c2[256*32*32];
__device__ float g_feat[512*16*16];
__device__ float g_rpn[512*16*16];
__device__ float g_obj[9*16*16];
__device__ float g_bd[36*16*16];
__device__ float g_props[2304*4];
__device__ float g_scores[2304];
__device__ int   g_topidx[TOPN];
__device__ float g_rois[TOPN*4];
__device__ int   g_geoi[1024*56];
__device__ float g_geow[1024*56];
__device__ u16 g_cAh[4096*576];
__device__ u16 g_cAl[4096*576];
__device__ u16 g_cBh[512*4608];
__device__ u16 g_cBl[512*4608];
__device__ u16 g_Ah[1024u*25088u];
__device__ u16 g_B1h[1024u*25088u];
__device__ u16 g_B2h[1024u*1024u];
__device__ u16 g_h1h[1024u*1024u];
__device__ float g_part[16u*1024u*1024u];
__device__ float g_h2[1024u*1024u];
__device__ float g_logits[TOPN*6];
__device__ float g_breg[TOPN*24];

__device__ __forceinline__ void split16(float v, u16& hi, u16& lo) {
    __half h = __float2half_rn(v);
    float res = (v - __half2float(h)) * LOSCALE;
    __half l = __float2half_rn(res);
    hi = *(u16*)&h;
    lo = *(u16*)&l;
}

// ---------------- conv0: smem-tiled 7x7 s2 ----------------
__global__ void conv0v2_kernel(const float* __restrict__ img,
                               const float* __restrict__ w,
                               const float* __restrict__ b,
                               float* __restrict__ out) {
    __shared__ float tile[3][37][72];
    __shared__ float ws[4][147];
    int tx = threadIdx.x, ty = threadIdx.y;
    int tid = ty*8 + tx;
    int oc0 = blockIdx.z * 4;
    int x0 = blockIdx.x * 32;
    int y0 = blockIdx.y * 16;
    int ixs = 2*x0 - 3, iys = 2*y0 - 3;
    const float mean[3] = {0.485f, 0.456f, 0.406f};
    const float istd[3] = {1.0f/0.229f, 1.0f/0.224f, 1.0f/0.225f};

    for (int i = tid; i < 3*37*72; i += 128) {
        int c = i / (37*72); int rem = i % (37*72);
        int iy = rem / 72, ix = rem % 72;
        int gy = iys + iy, gx = ixs + ix;
        float v = 0.0f;
        if (gy >= 0 && gy < 512 && gx >= 0 && gx < 512 && ix < 69)
            v = (img[(c*512 + gy)*512 + gx] - mean[c]) * istd[c];
        tile[c][iy][ix] = v;
    }
    for (int i = tid; i < 4*147; i += 128)
        ws[i/147][i%147] = w[(size_t)(oc0 + i/147)*147 + i%147];
    __syncthreads();

    float acc[4][4];
    #pragma unroll
    for (int oc = 0; oc < 4; oc++) {
        float bb = b[oc0+oc];
        #pragma unroll
        for (int xo = 0; xo < 4; xo++) acc[oc][xo] = bb;
    }
    for (int c = 0; c < 3; c++) {
        #pragma unroll
        for (int ky = 0; ky < 7; ky++) {
            const float* row = tile[c][2*ty + ky];
            float v[13];
            #pragma unroll
            for (int j = 0; j < 13; j++) v[j] = row[8*tx + j];
            #pragma unroll
            for (int kx = 0; kx < 7; kx++) {
                float w0 = ws[0][c*49 + ky*7 + kx];
                float w1 = ws[1][c*49 + ky*7 + kx];
                float w2 = ws[2][c*49 + ky*7 + kx];
                float w3 = ws[3][c*49 + ky*7 + kx];
                #pragma unroll
                for (int xo = 0; xo < 4; xo++) {
                    float vv = v[2*xo + kx];
                    acc[0][xo] = fmaf(vv, w0, acc[0][xo]);
                    acc[1][xo] = fmaf(vv, w1, acc[1][xo]);
                    acc[2][xo] = fmaf(vv, w2, acc[2][xo]);
                    acc[3][xo] = fmaf(vv, w3, acc[3][xo]);
                }
            }
        }
    }
    int y = y0 + ty;
    #pragma unroll
    for (int oc = 0; oc < 4; oc++)
        #pragma unroll
        for (int xo = 0; xo < 4; xo++)
            out[(size_t)(oc0+oc)*65536 + y*256 + x0 + tx*4 + xo] = fmaxf(acc[oc][xo], 0.0f);
}

// ---------------- maxpool 3x3 s2 p1 ----------------
__global__ void maxpool_kernel(const float* __restrict__ in, float* __restrict__ out) {
    int idx = blockIdx.x * 256 + threadIdx.x;
    if (idx >= 64*128*128) return;
    int x = idx & 127;
    int y = (idx >> 7) & 127;
    int c = idx >> 14;
    float m = -INFINITY;
    #pragma unroll
    for (int dy = 0; dy < 3; dy++) {
        int iy = 2*y - 1 + dy;
        if (iy < 0 || iy >= 256) continue;
        #pragma unroll
        for (int dx = 0; dx < 3; dx++) {
            int ix = 2*x - 1 + dx;
            if (ix < 0 || ix >= 256) continue;
            m = fmaxf(m, in[(c*256 + iy)*256 + ix]);
        }
    }
    out[idx] = m;
}

// ---------------- im2col + split ----------------
__global__ void im2col_kernel(const float* __restrict__ in,
                              u16* __restrict__ Ah, u16* __restrict__ Al,
                              int Cin, int Hin, int Hout, int stride, int total) {
    int t = blockIdx.x * 256 + threadIdx.x;
    if (t >= total) return;
    int K = Cin * 9;
    int pix = t / K, col = t - pix * K;
    int c = col / 9, k = col - c * 9;
    int ky = k / 3, kx = k - ky * 3;
    int y = pix / Hout, x = pix - y * Hout;
    int gy = y*stride - 1 + ky, gx = x*stride - 1 + kx;
    float v = 0.0f;
    if (gy >= 0 && gy < Hin && gx >= 0 && gx < Hin)
        v = in[(size_t)c*Hin*Hin + gy*Hin + gx];
    split16(v, Ah[t], Al[t]);
}

// ---------------- weight split ----------------
__global__ void wsplit_kernel(const float* __restrict__ W,
                              u16* __restrict__ Bh, u16* __restrict__ Bl, int total) {
    int t = blockIdx.x * 256 + threadIdx.x;
    if (t >= total) return;
    split16(W[t], Bh[t], Bl[t]);
}

// ---------------- mma helpers ----------------
__device__ __forceinline__ void mma16816_f32(float& d0, float& d1, float& d2, float& d3,
                                             uint32_t a0, uint32_t a1, uint32_t a2, uint32_t a3,
                                             uint32_t b0, uint32_t b1) {
    asm volatile("mma.sync.aligned.m16n8k16.row.col.f32.f16.f16.f32 "
                 "{%0,%1,%2,%3}, {%4,%5,%6,%7}, {%8,%9}, {%0,%1,%2,%3};\n"
                 : "+f"(d0), "+f"(d1), "+f"(d2), "+f"(d3)
                 : "r"(a0), "r"(a1), "r"(a2), "r"(a3), "r"(b0), "r"(b1));
}
__device__ __forceinline__ void cpasync16(uint32_t dst, const void* src) {
    asm volatile("cp.async.cg.shared.global [%0], [%1], 16;\n" :: "r"(dst), "l"(src));
}
__device__ __forceinline__ void ldsm_x4(uint32_t& r0, uint32_t& r1, uint32_t& r2, uint32_t& r3,
                                        uint32_t addr) {
    asm volatile("ldmatrix.sync.aligned.m8n8.x4.shared.b16 {%0,%1,%2,%3}, [%4];\n"
                 : "=r"(r0), "=r"(r1), "=r"(r2), "=r"(r3) : "r"(addr));
}

#define LDK 24

// ---------------- 3-pass split-fp16 GEMM (conv path) ----------------
__global__ void __launch_bounds__(256)
gemm_split3_kernel(const u16* __restrict__ Ah, const u16* __restrict__ Al,
                   const u16* __restrict__ Bh, const u16* __restrict__ Bl,
                   float* __restrict__ part, int K, int stages, int N) {
    __shared__ __align__(16) u16 sm[2][4][128*LDK];
    int tid = threadIdx.x;
    int wid = tid >> 5, lane = tid & 31;
    int wm = (wid & 1) * 64;
    int wn = (wid >> 1) * 32;
    int g = lane >> 2, tig = lane & 3;
    int r8 = lane & 7, q = lane >> 3;
    int bm = blockIdx.y * 128, bn = blockIdx.x * 128;
    int kbase = blockIdx.z * stages * 16;

    float acc[16][4], accx[16][4];
    #pragma unroll
    for (int i = 0; i < 16; i++)
        #pragma unroll
        for (int j = 0; j < 4; j++) { acc[i][j] = 0.0f; accx[i][j] = 0.0f; }

    uint32_t smb = (uint32_t)__cvta_generic_to_shared(&sm[0][0][0]);
    const uint32_t MAT = 128*LDK*2;
    const uint32_t BUF = 4*MAT;
    uint32_t offA = (uint32_t)(((wm + (q & 1)*8 + r8)*LDK + (q >> 1)*8) * 2);
    uint32_t offB = (uint32_t)(((wn + (q >> 1)*8 + r8)*LDK + (q & 1)*8) * 2);

    auto load_stage = [&](int buf, int s) {
        int kpos0 = kbase + s * 16;
        #pragma unroll
        for (int l = 0; l < 4; l++) {
            int idx = l * 256 + tid;
            int pl = idx >> 8;
            int rr = (idx & 255) >> 1;
            int half = idx & 1;
            int kpos = kpos0 + half * 8;
            const u16* src;
            if (pl == 0)      src = Ah + (size_t)(bm + rr)*K + kpos;
            else if (pl == 1) src = Al + (size_t)(bm + rr)*K + kpos;
            else if (pl == 2) src = Bh + (size_t)(bn + rr)*K + kpos;
            else              src = Bl + (size_t)(bn + rr)*K + kpos;
            uint32_t dst = (uint32_t)__cvta_generic_to_shared(&sm[buf][pl][rr*LDK + half*8]);
            cpasync16(dst, src);
        }
        asm volatile("cp.async.commit_group;\n");
    };

    load_stage(0, 0);

    for (int s = 0; s < stages; s++) {
        if (s + 1 < stages) {
            load_stage((s + 1) & 1, s + 1);
            asm volatile("cp.async.wait_group 1;\n");
        } else {
            asm volatile("cp.async.wait_group 0;\n");
        }
        __syncthreads();
        uint32_t base = smb + (uint32_t)(s & 1)*BUF;
        uint32_t aAh = base + offA;
        uint32_t aAl = base + MAT + offA;
        uint32_t aBh = base + 2*MAT + offB;
        uint32_t aBl = base + 3*MAT + offB;

        uint32_t bh[4][2], bl[4][2], ah[4][4], al[4][4];
        #pragma unroll
        for (int p = 0; p < 2; p++) {
            ldsm_x4(bh[2*p][0], bh[2*p][1], bh[2*p+1][0], bh[2*p+1][1], aBh + p*16*LDK*2);
            ldsm_x4(bl[2*p][0], bl[2*p][1], bl[2*p+1][0], bl[2*p+1][1], aBl + p*16*LDK*2);
        }
        #pragma unroll
        for (int mi = 0; mi < 4; mi++) {
            ldsm_x4(ah[mi][0], ah[mi][1], ah[mi][2], ah[mi][3], aAh + mi*16*LDK*2);
            ldsm_x4(al[mi][0], al[mi][1], al[mi][2], al[mi][3], aAl + mi*16*LDK*2);
        }

        #pragma unroll
        for (int mi = 0; mi < 4; mi++)
            #pragma unroll
            for (int ni = 0; ni < 4; ni++) {
                float* d = acc[mi*4 + ni];
                mma16816_f32(d[0], d[1], d[2], d[3],
                             ah[mi][0], ah[mi][1], ah[mi][2], ah[mi][3], bh[ni][0], bh[ni][1]);
            }
        #pragma unroll
        for (int mi = 0; mi < 4; mi++)
            #pragma unroll
            for (int ni = 0; ni < 4; ni++) {
                float* d = accx[mi*4 + ni];
                mma16816_f32(d[0], d[1], d[2], d[3],
                             ah[mi][0], ah[mi][1], ah[mi][2], ah[mi][3], bl[ni][0], bl[ni][1]);
            }
        #pragma unroll
        for (int mi = 0; mi < 4; mi++)
            #pragma unroll
            for (int ni = 0; ni < 4; ni++) {
                float* d = accx[mi*4 + ni];
                mma16816_f32(d[0], d[1], d[2], d[3],
                             al[mi][0], al[mi][1], al[mi][2], al[mi][3], bh[ni][0], bh[ni][1]);
            }
        __syncthreads();
    }

    size_t MN = (size_t)gridDim.y * 128 * N;
    float* cbase = part + (size_t)blockIdx.z * MN;
    #pragma unroll
    for (int mi = 0; mi < 4; mi++) {
        #pragma unroll
        for (int ni = 0; ni < 4; ni++) {
            int row = bm + wm + mi*16 + g;
            int col = bn + wn + ni*8 + 2*tig;
            float* d = acc[mi*4 + ni];
            float* x = accx[mi*4 + ni];
            *(float2*)&cbase[(size_t)row*N + col] =
                make_float2(fmaf(x[0], INVLOSCALE, d[0]), fmaf(x[1], INVLOSCALE, d[1]));
            *(float2*)&cbase[(size_t)(row+8)*N + col] =
                make_float2(fmaf(x[2], INVLOSCALE, d[2]), fmaf(x[3], INVLOSCALE, d[3]));
        }
    }
}

// reduce conv partials [z][pix][oc] -> CHW + bias + relu
__global__ void creduceT_kernel(const float* __restrict__ part,
                                const float* __restrict__ bias,
                                float* __restrict__ out, int M, int N, int z) {
    int idx = blockIdx.x * 256 + threadIdx.x;
    if (idx >= M*N) return;
    int pix = idx / N, oc = idx - pix*N;
    float s = bias[oc];
    size_t MN = (size_t)M*N;
    for (int i = 0; i < z; i++) s += part[i*MN + idx];
    out[(size_t)oc*M + pix] = fmaxf(s, 0.0f);
}

// ---------------- merged RPN 1x1 heads ----------------
__global__ void rpnheads_kernel(const float* __restrict__ in,
                                const float* __restrict__ clsw, const float* __restrict__ clsb,
                                const float* __restrict__ bbw, const float* __restrict__ bbb,
                                float* __restrict__ obj, float* __restrict__ bd) {
    int o = blockIdx.x;
    int p = threadIdx.x;
    const float* w;
    float acc;
    if (o < 9) { w = clsw + o*512; acc = clsb[o]; }
    else       { w = bbw + (o-9)*512; acc = bbb[o-9]; }
    for (int c = 0; c < 512; c++)
        acc = fmaf(in[c*256 + p], w[c], acc);
    if (o < 9) obj[o*256 + p] = acc;
    else       bd[(o-9)*256 + p] = acc;
}

// ---------------- RPN decode ----------------
__global__ void rpn_decode_kernel(const float* __restrict__ obj,
                                  const float* __restrict__ bd,
                                  float* __restrict__ props,
                                  float* __restrict__ scores) {
    int i = blockIdx.x * 256 + threadIdx.x;
    if (i >= 2304) return;
    int a = i % 9;
    int cell = i / 9;
    int wq = cell % 16;
    int hq = cell / 16;
    int pix = hq*16 + wq;
    scores[i] = obj[a*256 + pix];

    const float ratios[3] = {0.5f, 1.0f, 2.0f};
    int r = a / 3, s = a % 3;
    float scale = 128.0f * (float)(1 << s);
    float hr = sqrtf(ratios[r]);
    float wr = 1.0f / hr;
    float hw = rintf(wr * scale * 0.5f);
    float hh = rintf(hr * scale * 0.5f);
    float sx = (float)(wq * 32), sy = (float)(hq * 32);
    float W = 2.0f*hw, H = 2.0f*hh;
    float cx = sx, cy = sy;

    float dx = bd[(a*4+0)*256 + pix];
    float dy = bd[(a*4+1)*256 + pix];
    float dw = fminf(bd[(a*4+2)*256 + pix], BBOX_CLAMP);
    float dh = fminf(bd[(a*4+3)*256 + pix], BBOX_CLAMP);
    float pcx = dx*W + cx, pcy = dy*H + cy;
    float pw = expf(dw)*W, ph = expf(dh)*H;
    props[i*4+0] = pcx - 0.5f*pw;
    props[i*4+1] = pcy - 0.5f*ph;
    props[i*4+2] = pcx + 0.5f*pw;
    props[i*4+3] = pcy + 0.5f*ph;
}

// ---------------- top-k bitonic ----------------
__device__ __forceinline__ bool tk_lt(float sa, int ia, float sb, int ib) {
    return (sa > sb) || (sa == sb && ia < ib);
}
__global__ void topk_kernel(const float* __restrict__ scores, int* __restrict__ topidx) {
    __shared__ float s[4096];
    __shared__ int   ind[4096];
    int tid = threadIdx.x;
    for (int i = tid; i < 4096; i += 1024) {
        s[i] = (i < 2304) ? scores[i] : -INFINITY;
        ind[i] = i;
    }
    __syncthreads();
    for (int k = 2; k <= 4096; k <<= 1) {
        for (int j = k >> 1; j > 0; j >>= 1) {
            for (int base = 0; base < 4096; base += 1024) {
                int i = base + tid;
                int ixj = i ^ j;
                if (ixj > i) {
                    bool up = ((i & k) == 0);
                    float si = s[i], sj = s[ixj];
                    int ii = ind[i], ij = ind[ixj];
                    bool swp = up ? tk_lt(sj, ij, si, ii) : tk_lt(si, ii, sj, ij);
                    if (swp) { s[i] = sj; s[ixj] = si; ind[i] = ij; ind[ixj] = ii; }
                }
            }
            __syncthreads();
        }
    }
    for (int i = tid; i < TOPN; i += 1024) topidx[i] = ind[i];
}

__global__ void gather_rois_kernel(const float* __restrict__ props,
                                   const int* __restrict__ topidx,
                                   float* __restrict__ rois) {
    int i = blockIdx.x * 256 + threadIdx.x;
    if (i >= TOPN) return;
    int idx = topidx[i];
    #pragma unroll
    for (int k = 0; k < 4; k++)
        rois[i*4+k] = fminf(fmaxf(props[idx*4+k], 0.0f), 512.0f);
}

// ---------------- roi geometry precompute ----------------
__global__ void roigeo_kernel(const float* __restrict__ rois,
                              int* __restrict__ geoi, float* __restrict__ geow) {
    int t = blockIdx.x * 256 + threadIdx.x;
    if (t >= 1024*28) return;
    int rr = t / 28, i = t % 28;
    int ii = i % 14;
    bool isY = i >= 14;
    int pp = ii >> 1, sl = (ii & 1) * 2;
    int base = rr*56 + (isY ? 28 : 0) + pp*4 + sl;
    if (rr >= TOPN) {
        geoi[base] = 0; geoi[base+1] = 0;
        geow[base] = 0.0f; geow[base+1] = 0.0f;
        return;
    }
    float c1 = rois[rr*4 + (isY ? 1 : 0)];
    float c2 = rois[rr*4 + (isY ? 3 : 2)];
    float lo = c1 * (1.0f/32.0f);
    float hi = c2 * (1.0f/32.0f);
    float sz = fmaxf(hi - lo, 1.0f);
    float g = ((float)ii + 0.5f) / 14.0f;
    float p = fminf(fmaxf(lo + g*sz, 0.0f), 15.0f);
    int p0 = (int)floorf(p);
    int p1 = min(p0 + 1, 15);
    float l = p - (float)p0;
    geoi[base] = p0; geoi[base+1] = p1;
    geow[base] = 0.5f * (1.0f - l); geow[base+1] = 0.5f * l;
}

// ---------------- ROI align v3 ----------------
__global__ void __launch_bounds__(256)
roi_align3_kernel(const float* __restrict__ feat,
                  const int* __restrict__ geoi, const float* __restrict__ geow,
                  u16* __restrict__ Ah) {
    __shared__ float ftile[16*256];
    __shared__ int   si[64*56];
    __shared__ float sw[64*56];
    int cg = blockIdx.x;
    int chunk = blockIdx.y;
    int tid = threadIdx.x;
    {
        const float4* src = (const float4*)(feat + (size_t)cg*16*256);
        float4* dst = (float4*)ftile;
        for (int i = tid; i < 1024; i += 256) dst[i] = src[i];
    }
    int gbase = chunk*64*56;
    for (int i = tid; i < 64*56; i += 256) {
        si[i] = geoi[gbase + i];
        sw[i] = geow[gbase + i];
    }
    __syncthreads();

    for (int rl = 0; rl < 64; rl++) {
        int rr = chunk*64 + rl;
        const int* gi = si + rl*56;
        const float* gw = sw + rl*56;
        for (int t = tid; t < 784; t += 256) {
            int cl = t / 49, p = t % 49;
            int py = p / 7, px = p % 7;
            const float* f = ftile + cl*256;
            float acc = 0.0f;
            #pragma unroll
            for (int a = 0; a < 4; a++) {
                const float* frow = f + gi[28 + py*4 + a]*16;
                float sv = 0.0f;
                #pragma unroll
                for (int bb = 0; bb < 4; bb++)
                    sv = fmaf(gw[px*4 + bb], frow[gi[px*4 + bb]], sv);
                acc = fmaf(gw[28 + py*4 + a], sv, acc);
            }
            __half h = __float2half_rn(acc);
            Ah[(size_t)rr*25088 + (size_t)(cg*16 + cl)*49 + p] = *(u16*)&h;
        }
    }
}

// ---------------- transpose + fp16 weights ----------------
__global__ void tsplit_kernel(const float* __restrict__ W,
                              u16* __restrict__ Th, int K, int N) {
    __shared__ float t[32][33];
    int n0 = blockIdx.x * 32, k0 = blockIdx.y * 32;
    int tx = threadIdx.x, ty = threadIdx.y;
    #pragma unroll
    for (int i = 0; i < 4; i++)
        t[ty + 8*i][tx] = W[(size_t)(k0 + ty + 8*i)*N + n0 + tx];
    __syncthreads();
    #pragma unroll
    for (int i = 0; i < 4; i++) {
        __half h = __float2half_rn(t[tx][ty + 8*i]);
        Th[(size_t)(n0 + ty + 8*i)*K + k0 + tx] = *(u16*)&h;
    }
}

// ---------------- single-pass fp16 tensor-core GEMM (fc path) ----------------
__global__ void __launch_bounds__(256)
gemm_fp16_kernel(const u16* __restrict__ A, const u16* __restrict__ B,
                 float* __restrict__ part, int K, int stages) {
    __shared__ __align__(16) u16 sm[2][2][128*LDK];
    int tid = threadIdx.x;
    int wid = tid >> 5, lane = tid & 31;
    int wm = (wid & 1) * 64;
    int wn = (wid >> 1) * 32;
    int g = lane >> 2, tig = lane & 3;
    int r8 = lane & 7, q = lane >> 3;
    int bm = blockIdx.y * 128, bn = blockIdx.x * 128;
    int kbase = blockIdx.z * stages * 16;

    float acc[16][4];
    #pragma unroll
    for (int i = 0; i < 16; i++)
        #pragma unroll
        for (int j = 0; j < 4; j++) acc[i][j] = 0.0f;

    uint32_t smb = (uint32_t)__cvta_generic_to_shared(&sm[0][0][0]);
    const uint32_t MAT = 128*LDK*2;
    const uint32_t BUF = 2*MAT;
    uint32_t offA = (uint32_t)(((wm + (q & 1)*8 + r8)*LDK + (q >> 1)*8) * 2);
    uint32_t offB = (uint32_t)(((wn + (q >> 1)*8 + r8)*LDK + (q & 1)*8) * 2);

    auto load_stage = [&](int buf, int s) {
        int kpos0 = kbase + s * 16;
        #pragma unroll
        for (int l = 0; l < 2; l++) {
            int idx = l * 256 + tid;
            int pl = idx >> 8;
            int rr = (idx & 255) >> 1;
            int half = idx & 1;
            const u16* src = (pl ? B + (size_t)(bn + rr)*K : A + (size_t)(bm + rr)*K)
                             + kpos0 + half*8;
            uint32_t dst = (uint32_t)__cvta_generic_to_shared(&sm[buf][pl][rr*LDK + half*8]);
            cpasync16(dst, src);
        }
        asm volatile("cp.async.commit_group;\n");
    };

    load_stage(0, 0);

    for (int s = 0; s < stages; s++) {
        if (s + 1 < stages) {
            load_stage((s + 1) & 1, s + 1);
            asm volatile("cp.async.wait_group 1;\n");
        } else {
            asm volatile("cp.async.wait_group 0;\n");
        }
        __syncthreads();
        uint32_t base = smb + (uint32_t)(s & 1)*BUF;
        uint32_t aA = base + offA;
        uint32_t aB = base + MAT + offB;

        uint32_t bh[4][2], ah[4][4];
        #pragma unroll
        for (int p = 0; p < 2; p++)
            ldsm_x4(bh[2*p][0], bh[2*p][1], bh[2*p+1][0], bh[2*p+1][1], aB + p*16*LDK*2);
        #pragma unroll
        for (int mi = 0; mi < 4; mi++)
            ldsm_x4(ah[mi][0], ah[mi][1], ah[mi][2], ah[mi][3], aA + mi*16*LDK*2);

        #pragma unroll
        for (int mi = 0; mi < 4; mi++)
            #pragma unroll
            for (int ni = 0; ni < 4; ni++) {
                float* d = acc[mi*4 + ni];
                mma16816_f32(d[0], d[1], d[2], d[3],
                             ah[mi][0], ah[mi][1], ah[mi][2], ah[mi][3], bh[ni][0], bh[ni][1]);
            }
        __syncthreads();
    }

    float* cbase = part + ((size_t)blockIdx.z << 20);
    #pragma unroll
    for (int mi = 0; mi < 4; mi++) {
        #pragma unroll
        for (int ni = 0; ni < 4; ni++) {
            int row = bm + wm + mi*16 + g;
            int col = bn + wn + ni*8 + 2*tig;
            float* d = acc[mi*4 + ni];
            *(float2*)&cbase[(size_t)row*1024 + col]     = make_float2(d[0], d[1]);
            *(float2*)&cbase[(size_t)(row+8)*1024 + col] = make_float2(d[2], d[3]);
        }
    }
}

// reduce fc1 partials -> relu -> fp16 h1 (z=8)
__global__ void reduce1_kernel(const float* __restrict__ part,
                               const float* __restrict__ bias,
                               u16* __restrict__ Hh) {
    size_t idx = (size_t)blockIdx.x * 256 + threadIdx.x;
    int n = (int)(idx & 1023);
    float s = bias[n];
    #pragma unroll
    for (int i = 0; i < 8; i++) s += part[((size_t)i << 20) + idx];
    s = fmaxf(s, 0.0f);
    __half h = __float2half_rn(s);
    Hh[idx] = *(u16*)&h;
}

// reduce fc2 partials -> relu -> f32 h2
__global__ void reduce2_kernel(const float* __restrict__ part,
                               const float* __restrict__ bias,
                               float* __restrict__ H) {
    size_t idx = (size_t)blockIdx.x * 256 + threadIdx.x;
    int n = (int)(idx & 1023);
    float s = bias[n];
    #pragma unroll
    for (int i = 0; i < 4; i++) s += part[((size_t)i << 20) + idx];
    H[idx] = fmaxf(s, 0.0f);
}

// ---------------- cls + bbox heads: block per roi ----------------
__global__ void __launch_bounds__(256)
fc_small2_kernel(const float* __restrict__ h,
                 const float* __restrict__ clsw, const float* __restrict__ clsb,
                 const float* __restrict__ bbw, const float* __restrict__ bbb,
                 float* __restrict__ logits, float* __restrict__ breg) {
    __shared__ float hs[1024];
    int r = blockIdx.x;
    int tid = threadIdx.x;
    const float* hp = h + (size_t)r*1024;
    for (int i = tid; i < 1024; i += 256) hs[i] = hp[i];
    __syncthreads();
    if (tid < 240) {
        int j = tid >> 3, part = tid & 7;
        float acc = 0.0f;
        if (j < 6) {
            for (int k = part; k < 1024; k += 8)
                acc = fmaf(hs[k], clsw[k*6 + j], acc);
        } else {
            int q = j - 6;
            for (int k = part; k < 1024; k += 8)
                acc = fmaf(hs[k], bbw[k*24 + q], acc);
        }
        #pragma unroll
        for (int off = 4; off; off >>= 1)
            acc += __shfl_down_sync(0xffffffff, acc, off);
        if (part == 0) {
            if (j < 6) logits[r*6 + j] = acc + clsb[j];
            else       breg[r*24 + (j-6)] = acc + bbb[j-6];
        }
    }
}

// ---------------- final ----------------
__global__ void final_kernel(const float* __restrict__ rois,
                             const float* __restrict__ logits,
                             const float* __restrict__ breg,
                             float* __restrict__ out) {
    int r = blockIdx.x * 128 + threadIdx.x;
    if (r >= TOPN) return;
    float l[6];
    float m = -INFINITY;
    #pragma unroll
    for (int i = 0; i < 6; i++) { l[i] = logits[r*6 + i]; m = fmaxf(m, l[i]); }
    float ssum = 0.0f;
    #pragma unroll
    for (int i = 0; i < 6; i++) { l[i] = expf(l[i] - m); ssum += l[i]; }
    float inv = 1.0f / ssum;

    float x1 = rois[r*4+0], y1 = rois[r*4+1], x2 = rois[r*4+2], y2 = rois[r*4+3];
    float W = x2 - x1, H = y2 - y1;
    float cx = x1 + 0.5f*W, cy = y1 + 0.5f*H;
    #pragma unroll
    for (int c = 1; c < 6; c++) {
        float dx = breg[r*24 + c*4+0] / 10.0f;
        float dy = breg[r*24 + c*4+1] / 10.0f;
        float dw = fminf(breg[r*24 + c*4+2] / 5.0f, BBOX_CLAMP);
        float dh = fminf(breg[r*24 + c*4+3] / 5.0f, BBOX_CLAMP);
        float pcx = dx*W + cx, pcy = dy*H + cy;
        float pw = expf(dw)*W, ph = expf(dh)*H;
        float bx1 = fminf(fmaxf(pcx - 0.5f*pw, 0.0f), 512.0f);
        float by1 = fminf(fmaxf(pcy - 0.5f*ph, 0.0f), 512.0f);
        float bx2 = fminf(fmaxf(pcx + 0.5f*pw, 0.0f), 512.0f);
        float by2 = fminf(fmaxf(pcy + 0.5f*ph, 0.0f), 512.0f);
        int o = r*25 + (c-1)*5;
        out[o+0] = bx1; out[o+1] = by1; out[o+2] = bx2; out[o+3] = by2;
        out[o+4] = l[c] * inv;
    }
}

// ---------------- launcher ----------------
extern "C" void kernel_launch(void* const* d_in, const int* in_sizes, int n_in,
                              void* d_out, int out_size) {
    const float* images     = (const float*)d_in[0];
    const float* c0_w       = (const float*)d_in[1];
    const float* c0_b       = (const float*)d_in[2];
    const float* c1_w       = (const float*)d_in[3];
    const float* c1_b       = (const float*)d_in[4];
    const float* c2_w       = (const float*)d_in[5];
    const float* c2_b       = (const float*)d_in[6];
    const float* c3_w       = (const float*)d_in[7];
    const float* c3_b       = (const float*)d_in[8];
    const float* rpn_conv_w = (const float*)d_in[9];
    const float* rpn_conv_b = (const float*)d_in[10];
    const float* rpn_cls_w  = (const float*)d_in[11];
    const float* rpn_cls_b  = (const float*)d_in[12];
    const float* rpn_bbox_w = (const float*)d_in[13];
    const float* rpn_bbox_b = (const float*)d_in[14];
    const float* fc1_w      = (const float*)d_in[15];
    const float* fc1_b      = (const float*)d_in[16];
    const float* fc2_w      = (const float*)d_in[17];
    const float* fc2_b      = (const float*)d_in[18];
    const float* cls_w      = (const float*)d_in[19];
    const float* cls_b      = (const float*)d_in[20];
    const float* bbox_w     = (const float*)d_in[21];
    const float* bbox_b     = (const float*)d_in[22];
    float* out = (float*)d_out;

    float *p_c0, *p_pool, *p_c1, *p_c2, *p_feat, *p_rpn, *p_obj, *p_bd;
    float *p_props, *p_scores, *p_rois, *p_part, *p_h2, *p_logits, *p_breg, *p_geow;
    int *p_topidx, *p_geoi;
    u16 *p_Ah, *p_B1h, *p_B2h, *p_h1h, *p_cAh, *p_cAl, *p_cBh, *p_cBl;
    cudaGetSymbolAddress((void**)&p_c0, g_c0);
    cudaGetSymbolAddress((void**)&p_pool, g_pool);
    cudaGetSymbolAddress((void**)&p_c1, g_c1);
    cudaGetSymbolAddress((void**)&p_c2, g_c2);
    cudaGetSymbolAddress((void**)&p_feat, g_feat);
    cudaGetSymbolAddress((void**)&p_rpn, g_rpn);
    cudaGetSymbolAddress((void**)&p_obj, g_obj);
    cudaGetSymbolAddress((void**)&p_bd, g_bd);
    cudaGetSymbolAddress((void**)&p_props, g_props);
    cudaGetSymbolAddress((void**)&p_scores, g_scores);
    cudaGetSymbolAddress((void**)&p_topidx, g_topidx);
    cudaGetSymbolAddress((void**)&p_rois, g_rois);
    cudaGetSymbolAddress((void**)&p_geoi, g_geoi);
    cudaGetSymbolAddress((void**)&p_geow, g_geow);
    cudaGetSymbolAddress((void**)&p_cAh, g_cAh);
    cudaGetSymbolAddress((void**)&p_cAl, g_cAl);
    cudaGetSymbolAddress((void**)&p_cBh, g_cBh);
    cudaGetSymbolAddress((void**)&p_cBl, g_cBl);
    cudaGetSymbolAddress((void**)&p_Ah, g_Ah);
    cudaGetSymbolAddress((void**)&p_B1h, g_B1h);
    cudaGetSymbolAddress((void**)&p_B2h, g_B2h);
    cudaGetSymbolAddress((void**)&p_h1h, g_h1h);
    cudaGetSymbolAddress((void**)&p_part, g_part);
    cudaGetSymbolAddress((void**)&p_h2, g_h2);
    cudaGetSymbolAddress((void**)&p_logits, g_logits);
    cudaGetSymbolAddress((void**)&p_breg, g_breg);

    // second stream for independent fc-weight transpose (round-13 config)
    static cudaStream_t s2 = 0;
    static cudaEvent_t evF = 0, evJ = 0;
    if (!s2) {
        cudaStreamCreateWithFlags(&s2, cudaStreamNonBlocking);
        cudaEventCreateWithFlags(&evF, cudaEventDisableTiming);
        cudaEventCreateWithFlags(&evJ, cudaEventDisableTiming);
    }
    cudaEventRecord(evF, 0);
    cudaStreamWaitEvent(s2, evF, 0);
    tsplit_kernel<<<dim3(1024/32, 25088/32), dim3(32,8), 0, s2>>>(fc1_w, p_B1h, 25088, 1024);
    tsplit_kernel<<<dim3(1024/32, 1024/32),  dim3(32,8), 0, s2>>>(fc2_w, p_B2h, 1024, 1024);
    cudaEventRecord(evJ, s2);

    // backbone: conv0 + pool, then implicit-GEMM convs (wsplits inline)
    conv0v2_kernel<<<dim3(8,16,16), dim3(8,16)>>>(images, c0_w, c0_b, p_c0);
    maxpool_kernel<<<(64*128*128 + 255)/256, 256>>>(p_c0, p_pool);

    // c1
    im2col_kernel<<<(4096*576 + 255)/256, 256>>>(p_pool, p_cAh, p_cAl, 64, 128, 64, 2, 4096*576);
    wsplit_kernel<<<(128*576 + 255)/256, 256>>>(c1_w, p_cBh, p_cBl, 128*576);
    gemm_split3_kernel<<<dim3(1,32,9), 256>>>(p_cAh, p_cAl, p_cBh, p_cBl, p_part, 576, 4, 128);
    creduceT_kernel<<<(4096*128 + 255)/256, 256>>>(p_part, c1_b, p_c1, 4096, 128, 9);

    // c2
    im2col_kernel<<<(1024*1152 + 255)/256, 256>>>(p_c1, p_cAh, p_cAl, 128, 64, 32, 2, 1024*1152);
    wsplit_kernel<<<(256*1152 + 255)/256, 256>>>(c2_w, p_cBh, p_cBl, 256*1152);
    gemm_split3_kernel<<<dim3(2,8,12), 256>>>(p_cAh, p_cAl, p_cBh, p_cBl, p_part, 1152, 6, 256);
    creduceT_kernel<<<(1024*256 + 255)/256, 256>>>(p_part, c2_b, p_c2, 1024, 256, 12);

    // c3
    im2col_kernel<<<(256*2304 + 255)/256, 256>>>(p_c2, p_cAh, p_cAl, 256, 32, 16, 2, 256*2304);
    wsplit_kernel<<<(512*2304 + 255)/256, 256>>>(c3_w, p_cBh, p_cBl, 512*2304);
    gemm_split3_kernel<<<dim3(4,2,18), 256>>>(p_cAh, p_cAl, p_cBh, p_cBl, p_part, 2304, 8, 512);
    creduceT_kernel<<<(256*512 + 255)/256, 256>>>(p_part, c3_b, p_feat, 256, 512, 18);

    // rpn conv
    im2col_kernel<<<(256*4608 + 255)/256, 256>>>(p_feat, p_cAh, p_cAl, 512, 16, 16, 1, 256*4608);
    wsplit_kernel<<<(512*4608 + 255)/256, 256>>>(rpn_conv_w, p_cBh, p_cBl, 512*4608);
    gemm_split3_kernel<<<dim3(4,2,24), 256>>>(p_cAh, p_cAl, p_cBh, p_cBl, p_part, 4608, 12, 512);
    creduceT_kernel<<<(256*512 + 255)/256, 256>>>(p_part, rpn_conv_b, p_rpn, 256, 512, 24);

    // RPN heads
    rpnheads_kernel<<<45, 256>>>(p_rpn, rpn_cls_w, rpn_cls_b, rpn_bbox_w, rpn_bbox_b, p_obj, p_bd);

    // proposals (round-13 separate kernels — propfuse rejected)
    rpn_decode_kernel<<<9, 256>>>(p_obj, p_bd, p_props, p_scores);
    topk_kernel<<<1, 1024>>>(p_scores, p_topidx);
    gather_rois_kernel<<<4, 256>>>(p_props, p_topidx, p_rois);
    roigeo_kernel<<<(1024*28 + 255)/256, 256>>>(p_rois, p_geoi, p_geow);

    // roi align -> fp16 A
    roi_align3_kernel<<<dim3(32,16), 256>>>(p_feat, p_geoi, p_geow, p_Ah);

    // join fc weights
    cudaStreamWaitEvent(0, evJ, 0);

    // fc1: K=25088, z=8 -> stages 196  (the ONE change vs the 821.6 baseline)
    gemm_fp16_kernel<<<dim3(8,8,8), 256>>>(p_Ah, p_B1h, p_part, 25088, 196);
    reduce1_kernel<<<(1024*1024)/256, 256>>>(p_part, fc1_b, p_h1h);

    // fc2: K=1024, z=4 -> stages 16
    gemm_fp16_kernel<<<dim3(8,8,4), 256>>>(p_h1h, p_B2h, p_part, 1024, 16);
    reduce2_kernel<<<(1024*1024)/256, 256>>>(p_part, fc2_b, p_h2);

    fc_small2_kernel<<<TOPN, 256>>>(p_h2, cls_w, cls_b, bbox_w, bbox_b, p_logits, p_breg);
    final_kernel<<<(TOPN + 127)/128, 128>>>(p_rois, p_logits, p_breg, out);
}

// round 17
// speedup vs baseline: 1.0182x; 1.0182x over previous
#include <cuda_runtime.h>
#include <cuda_fp16.h>
#include <math.h>
#include <stdint.h>

#define TOPN 1000
#define BBOX_CLAMP 4.135166556742356f
#define LOSCALE 2048.0f
#define INVLOSCALE (1.0f/2048.0f)
typedef unsigned short u16;

// ---------------- scratch (device globals) ----------------
__device__ float g_c0[64*256*256];
__device__ float g_pool[64*128*128];
__device__ float g_c1[128*64*64];
__device__ float g_c2[256*32*32];
__device__ float g_feat[512*16*16];
__device__ float g_rpn[512*16*16];
__device__ float g_obj[9*16*16];
__device__ float g_bd[36*16*16];
__device__ float g_props[2304*4];
__device__ float g_scores[2304];
__device__ int   g_topidx[TOPN];
__device__ float g_rois[TOPN*4];
__device__ int   g_geoi[1024*56];
__device__ float g_geow[1024*56];
__device__ u16 g_cAh[4096*576];
__device__ u16 g_cAl[4096*576];
__device__ u16 g_cBh[512*4608];
__device__ u16 g_cBl[512*4608];
__device__ u16 g_Ah[1024u*25088u];
__device__ u16 g_B1h[1024u*25088u];
__device__ u16 g_B2h[1024u*1024u];
__device__ u16 g_h1h[1024u*1024u];
__device__ float g_part[16u*1024u*1024u];   // conv fp32 partials; fc path reuses as fp16
__device__ float g_h2[1024u*1024u];
__device__ float g_logits[TOPN*6];
__device__ float g_breg[TOPN*24];

__device__ __forceinline__ void split16(float v, u16& hi, u16& lo) {
    __half h = __float2half_rn(v);
    float res = (v - __half2float(h)) * LOSCALE;
    __half l = __float2half_rn(res);
    hi = *(u16*)&h;
    lo = *(u16*)&l;
}

// ---------------- conv0: smem-tiled 7x7 s2 ----------------
__global__ void conv0v2_kernel(const float* __restrict__ img,
                               const float* __restrict__ w,
                               const float* __restrict__ b,
                               float* __restrict__ out) {
    __shared__ float tile[3][37][72];
    __shared__ float ws[4][147];
    int tx = threadIdx.x, ty = threadIdx.y;
    int tid = ty*8 + tx;
    int oc0 = blockIdx.z * 4;
    int x0 = blockIdx.x * 32;
    int y0 = blockIdx.y * 16;
    int ixs = 2*x0 - 3, iys = 2*y0 - 3;
    const float mean[3] = {0.485f, 0.456f, 0.406f};
    const float istd[3] = {1.0f/0.229f, 1.0f/0.224f, 1.0f/0.225f};

    for (int i = tid; i < 3*37*72; i += 128) {
        int c = i / (37*72); int rem = i % (37*72);
        int iy = rem / 72, ix = rem % 72;
        int gy = iys + iy, gx = ixs + ix;
        float v = 0.0f;
        if (gy >= 0 && gy < 512 && gx >= 0 && gx < 512 && ix < 69)
            v = (img[(c*512 + gy)*512 + gx] - mean[c]) * istd[c];
        tile[c][iy][ix] = v;
    }
    for (int i = tid; i < 4*147; i += 128)
        ws[i/147][i%147] = w[(size_t)(oc0 + i/147)*147 + i%147];
    __syncthreads();

    float acc[4][4];
    #pragma unroll
    for (int oc = 0; oc < 4; oc++) {
        float bb = b[oc0+oc];
        #pragma unroll
        for (int xo = 0; xo < 4; xo++) acc[oc][xo] = bb;
    }
    for (int c = 0; c < 3; c++) {
        #pragma unroll
        for (int ky = 0; ky < 7; ky++) {
            const float* row = tile[c][2*ty + ky];
            float v[13];
            #pragma unroll
            for (int j = 0; j < 13; j++) v[j] = row[8*tx + j];
            #pragma unroll
            for (int kx = 0; kx < 7; kx++) {
                float w0 = ws[0][c*49 + ky*7 + kx];
                float w1 = ws[1][c*49 + ky*7 + kx];
                float w2 = ws[2][c*49 + ky*7 + kx];
                float w3 = ws[3][c*49 + ky*7 + kx];
                #pragma unroll
                for (int xo = 0; xo < 4; xo++) {
                    float vv = v[2*xo + kx];
                    acc[0][xo] = fmaf(vv, w0, acc[0][xo]);
                    acc[1][xo] = fmaf(vv, w1, acc[1][xo]);
                    acc[2][xo] = fmaf(vv, w2, acc[2][xo]);
                    acc[3][xo] = fmaf(vv, w3, acc[3][xo]);
                }
            }
        }
    }
    int y = y0 + ty;
    #pragma unroll
    for (int oc = 0; oc < 4; oc++)
        #pragma unroll
        for (int xo = 0; xo < 4; xo++)
            out[(size_t)(oc0+oc)*65536 + y*256 + x0 + tx*4 + xo] = fmaxf(acc[oc][xo], 0.0f);
}

// ---------------- maxpool 3x3 s2 p1 ----------------
__global__ void maxpool_kernel(const float* __restrict__ in, float* __restrict__ out) {
    int idx = blockIdx.x * 256 + threadIdx.x;
    if (idx >= 64*128*128) return;
    int x = idx & 127;
    int y = (idx >> 7) & 127;
    int c = idx >> 14;
    float m = -INFINITY;
    #pragma unroll
    for (int dy = 0; dy < 3; dy++) {
        int iy = 2*y - 1 + dy;
        if (iy < 0 || iy >= 256) continue;
        #pragma unroll
        for (int dx = 0; dx < 3; dx++) {
            int ix = 2*x - 1 + dx;
            if (ix < 0 || ix >= 256) continue;
            m = fmaxf(m, in[(c*256 + iy)*256 + ix]);
        }
    }
    out[idx] = m;
}

// ---------------- im2col + split ----------------
__global__ void im2col_kernel(const float* __restrict__ in,
                              u16* __restrict__ Ah, u16* __restrict__ Al,
                              int Cin, int Hin, int Hout, int stride, int total) {
    int t = blockIdx.x * 256 + threadIdx.x;
    if (t >= total) return;
    int K = Cin * 9;
    int pix = t / K, col = t - pix * K;
    int c = col / 9, k = col - c * 9;
    int ky = k / 3, kx = k - ky * 3;
    int y = pix / Hout, x = pix - y * Hout;
    int gy = y*stride - 1 + ky, gx = x*stride - 1 + kx;
    float v = 0.0f;
    if (gy >= 0 && gy < Hin && gx >= 0 && gx < Hin)
        v = in[(size_t)c*Hin*Hin + gy*Hin + gx];
    split16(v, Ah[t], Al[t]);
}

// ---------------- weight split ----------------
__global__ void wsplit_kernel(const float* __restrict__ W,
                              u16* __restrict__ Bh, u16* __restrict__ Bl, int total) {
    int t = blockIdx.x * 256 + threadIdx.x;
    if (t >= total) return;
    split16(W[t], Bh[t], Bl[t]);
}

// ---------------- mma helpers ----------------
__device__ __forceinline__ void mma16816_f32(float& d0, float& d1, float& d2, float& d3,
                                             uint32_t a0, uint32_t a1, uint32_t a2, uint32_t a3,
                                             uint32_t b0, uint32_t b1) {
    asm volatile("mma.sync.aligned.m16n8k16.row.col.f32.f16.f16.f32 "
                 "{%0,%1,%2,%3}, {%4,%5,%6,%7}, {%8,%9}, {%0,%1,%2,%3};\n"
                 : "+f"(d0), "+f"(d1), "+f"(d2), "+f"(d3)
                 : "r"(a0), "r"(a1), "r"(a2), "r"(a3), "r"(b0), "r"(b1));
}
__device__ __forceinline__ void cpasync16(uint32_t dst, const void* src) {
    asm volatile("cp.async.cg.shared.global [%0], [%1], 16;\n" :: "r"(dst), "l"(src));
}
__device__ __forceinline__ void ldsm_x4(uint32_t& r0, uint32_t& r1, uint32_t& r2, uint32_t& r3,
                                        uint32_t addr) {
    asm volatile("ldmatrix.sync.aligned.m8n8.x4.shared.b16 {%0,%1,%2,%3}, [%4];\n"
                 : "=r"(r0), "=r"(r1), "=r"(r2), "=r"(r3) : "r"(addr));
}

#define LDK 24

// ---------------- 3-pass split-fp16 GEMM (conv path, fp32 partials) ----------------
__global__ void __launch_bounds__(256)
gemm_split3_kernel(const u16* __restrict__ Ah, const u16* __restrict__ Al,
                   const u16* __restrict__ Bh, const u16* __restrict__ Bl,
                   float* __restrict__ part, int K, int stages, int N) {
    __shared__ __align__(16) u16 sm[2][4][128*LDK];
    int tid = threadIdx.x;
    int wid = tid >> 5, lane = tid & 31;
    int wm = (wid & 1) * 64;
    int wn = (wid >> 1) * 32;
    int g = lane >> 2, tig = lane & 3;
    int r8 = lane & 7, q = lane >> 3;
    int bm = blockIdx.y * 128, bn = blockIdx.x * 128;
    int kbase = blockIdx.z * stages * 16;

    float acc[16][4], accx[16][4];
    #pragma unroll
    for (int i = 0; i < 16; i++)
        #pragma unroll
        for (int j = 0; j < 4; j++) { acc[i][j] = 0.0f; accx[i][j] = 0.0f; }

    uint32_t smb = (uint32_t)__cvta_generic_to_shared(&sm[0][0][0]);
    const uint32_t MAT = 128*LDK*2;
    const uint32_t BUF = 4*MAT;
    uint32_t offA = (uint32_t)(((wm + (q & 1)*8 + r8)*LDK + (q >> 1)*8) * 2);
    uint32_t offB = (uint32_t)(((wn + (q >> 1)*8 + r8)*LDK + (q & 1)*8) * 2);

    auto load_stage = [&](int buf, int s) {
        int kpos0 = kbase + s * 16;
        #pragma unroll
        for (int l = 0; l < 4; l++) {
            int idx = l * 256 + tid;
            int pl = idx >> 8;
            int rr = (idx & 255) >> 1;
            int half = idx & 1;
            int kpos = kpos0 + half * 8;
            const u16* src;
            if (pl == 0)      src = Ah + (size_t)(bm + rr)*K + kpos;
            else if (pl == 1) src = Al + (size_t)(bm + rr)*K + kpos;
            else if (pl == 2) src = Bh + (size_t)(bn + rr)*K + kpos;
            else              src = Bl + (size_t)(bn + rr)*K + kpos;
            uint32_t dst = (uint32_t)__cvta_generic_to_shared(&sm[buf][pl][rr*LDK + half*8]);
            cpasync16(dst, src);
        }
        asm volatile("cp.async.commit_group;\n");
    };

    load_stage(0, 0);

    for (int s = 0; s < stages; s++) {
        if (s + 1 < stages) {
            load_stage((s + 1) & 1, s + 1);
            asm volatile("cp.async.wait_group 1;\n");
        } else {
            asm volatile("cp.async.wait_group 0;\n");
        }
        __syncthreads();
        uint32_t base = smb + (uint32_t)(s & 1)*BUF;
        uint32_t aAh = base + offA;
        uint32_t aAl = base + MAT + offA;
        uint32_t aBh = base + 2*MAT + offB;
        uint32_t aBl = base + 3*MAT + offB;

        uint32_t bh[4][2], bl[4][2], ah[4][4], al[4][4];
        #pragma unroll
        for (int p = 0; p < 2; p++) {
            ldsm_x4(bh[2*p][0], bh[2*p][1], bh[2*p+1][0], bh[2*p+1][1], aBh + p*16*LDK*2);
            ldsm_x4(bl[2*p][0], bl[2*p][1], bl[2*p+1][0], bl[2*p+1][1], aBl + p*16*LDK*2);
        }
        #pragma unroll
        for (int mi = 0; mi < 4; mi++) {
            ldsm_x4(ah[mi][0], ah[mi][1], ah[mi][2], ah[mi][3], aAh + mi*16*LDK*2);
            ldsm_x4(al[mi][0], al[mi][1], al[mi][2], al[mi][3], aAl + mi*16*LDK*2);
        }

        #pragma unroll
        for (int mi = 0; mi < 4; mi++)
            #pragma unroll
            for (int ni = 0; ni < 4; ni++) {
                float* d = acc[mi*4 + ni];
                mma16816_f32(d[0], d[1], d[2], d[3],
                             ah[mi][0], ah[mi][1], ah[mi][2], ah[mi][3], bh[ni][0], bh[ni][1]);
            }
        #pragma unroll
        for (int mi = 0; mi < 4; mi++)
            #pragma unroll
            for (int ni = 0; ni < 4; ni++) {
                float* d = accx[mi*4 + ni];
                mma16816_f32(d[0], d[1], d[2], d[3],
                             ah[mi][0], ah[mi][1], ah[mi][2], ah[mi][3], bl[ni][0], bl[ni][1]);
            }
        #pragma unroll
        for (int mi = 0; mi < 4; mi++)
            #pragma unroll
            for (int ni = 0; ni < 4; ni++) {
                float* d = accx[mi*4 + ni];
                mma16816_f32(d[0], d[1], d[2], d[3],
                             al[mi][0], al[mi][1], al[mi][2], al[mi][3], bh[ni][0], bh[ni][1]);
            }
        __syncthreads();
    }

    size_t MN = (size_t)gridDim.y * 128 * N;
    float* cbase = part + (size_t)blockIdx.z * MN;
    #pragma unroll
    for (int mi = 0; mi < 4; mi++) {
        #pragma unroll
        for (int ni = 0; ni < 4; ni++) {
            int row = bm + wm + mi*16 + g;
            int col = bn + wn + ni*8 + 2*tig;
            float* d = acc[mi*4 + ni];
            float* x = accx[mi*4 + ni];
            *(float2*)&cbase[(size_t)row*N + col] =
                make_float2(fmaf(x[0], INVLOSCALE, d[0]), fmaf(x[1], INVLOSCALE, d[1]));
            *(float2*)&cbase[(size_t)(row+8)*N + col] =
                make_float2(fmaf(x[2], INVLOSCALE, d[2]), fmaf(x[3], INVLOSCALE, d[3]));
        }
    }
}

// reduce conv partials [z][pix][oc] -> CHW + bias + relu
__global__ void creduceT_kernel(const float* __restrict__ part,
                                const float* __restrict__ bias,
                                float* __restrict__ out, int M, int N, int z) {
    int idx = blockIdx.x * 256 + threadIdx.x;
    if (idx >= M*N) return;
    int pix = idx / N, oc = idx - pix*N;
    float s = bias[oc];
    size_t MN = (size_t)M*N;
    for (int i = 0; i < z; i++) s += part[i*MN + idx];
    out[(size_t)oc*M + pix] = fmaxf(s, 0.0f);
}

// ---------------- merged RPN 1x1 heads ----------------
__global__ void rpnheads_kernel(const float* __restrict__ in,
                                const float* __restrict__ clsw, const float* __restrict__ clsb,
                                const float* __restrict__ bbw, const float* __restrict__ bbb,
                                float* __restrict__ obj, float* __restrict__ bd) {
    int o = blockIdx.x;
    int p = threadIdx.x;
    const float* w;
    float acc;
    if (o < 9) { w = clsw + o*512; acc = clsb[o]; }
    else       { w = bbw + (o-9)*512; acc = bbb[o-9]; }
    for (int c = 0; c < 512; c++)
        acc = fmaf(in[c*256 + p], w[c], acc);
    if (o < 9) obj[o*256 + p] = acc;
    else       bd[(o-9)*256 + p] = acc;
}

// ---------------- RPN decode ----------------
__global__ void rpn_decode_kernel(const float* __restrict__ obj,
                                  const float* __restrict__ bd,
                                  float* __restrict__ props,
                                  float* __restrict__ scores) {
    int i = blockIdx.x * 256 + threadIdx.x;
    if (i >= 2304) return;
    int a = i % 9;
    int cell = i / 9;
    int wq = cell % 16;
    int hq = cell / 16;
    int pix = hq*16 + wq;
    scores[i] = obj[a*256 + pix];

    const float ratios[3] = {0.5f, 1.0f, 2.0f};
    int r = a / 3, s = a % 3;
    float scale = 128.0f * (float)(1 << s);
    float hr = sqrtf(ratios[r]);
    float wr = 1.0f / hr;
    float hw = rintf(wr * scale * 0.5f);
    float hh = rintf(hr * scale * 0.5f);
    float sx = (float)(wq * 32), sy = (float)(hq * 32);
    float W = 2.0f*hw, H = 2.0f*hh;
    float cx = sx, cy = sy;

    float dx = bd[(a*4+0)*256 + pix];
    float dy = bd[(a*4+1)*256 + pix];
    float dw = fminf(bd[(a*4+2)*256 + pix], BBOX_CLAMP);
    float dh = fminf(bd[(a*4+3)*256 + pix], BBOX_CLAMP);
    float pcx = dx*W + cx, pcy = dy*H + cy;
    float pw = expf(dw)*W, ph = expf(dh)*H;
    props[i*4+0] = pcx - 0.5f*pw;
    props[i*4+1] = pcy - 0.5f*ph;
    props[i*4+2] = pcx + 0.5f*pw;
    props[i*4+3] = pcy + 0.5f*ph;
}

// ---------------- top-k bitonic ----------------
__device__ __forceinline__ bool tk_lt(float sa, int ia, float sb, int ib) {
    return (sa > sb) || (sa == sb && ia < ib);
}
__global__ void topk_kernel(const float* __restrict__ scores, int* __restrict__ topidx) {
    __shared__ float s[4096];
    __shared__ int   ind[4096];
    int tid = threadIdx.x;
    for (int i = tid; i < 4096; i += 1024) {
        s[i] = (i < 2304) ? scores[i] : -INFINITY;
        ind[i] = i;
    }
    __syncthreads();
    for (int k = 2; k <= 4096; k <<= 1) {
        for (int j = k >> 1; j > 0; j >>= 1) {
            for (int base = 0; base < 4096; base += 1024) {
                int i = base + tid;
                int ixj = i ^ j;
                if (ixj > i) {
                    bool up = ((i & k) == 0);
                    float si = s[i], sj = s[ixj];
                    int ii = ind[i], ij = ind[ixj];
                    bool swp = up ? tk_lt(sj, ij, si, ii) : tk_lt(si, ii, sj, ij);
                    if (swp) { s[i] = sj; s[ixj] = si; ind[i] = ij; ind[ixj] = ii; }
                }
            }
            __syncthreads();
        }
    }
    for (int i = tid; i < TOPN; i += 1024) topidx[i] = ind[i];
}

__global__ void gather_rois_kernel(const float* __restrict__ props,
                                   const int* __restrict__ topidx,
                                   float* __restrict__ rois) {
    int i = blockIdx.x * 256 + threadIdx.x;
    if (i >= TOPN) return;
    int idx = topidx[i];
    #pragma unroll
    for (int k = 0; k < 4; k++)
        rois[i*4+k] = fminf(fmaxf(props[idx*4+k], 0.0f), 512.0f);
}

// ---------------- roi geometry precompute ----------------
__global__ void roigeo_kernel(const float* __restrict__ rois,
                              int* __restrict__ geoi, float* __restrict__ geow) {
    int t = blockIdx.x * 256 + threadIdx.x;
    if (t >= 1024*28) return;
    int rr = t / 28, i = t % 28;
    int ii = i % 14;
    bool isY = i >= 14;
    int pp = ii >> 1, sl = (ii & 1) * 2;
    int base = rr*56 + (isY ? 28 : 0) + pp*4 + sl;
    if (rr >= TOPN) {
        geoi[base] = 0; geoi[base+1] = 0;
        geow[base] = 0.0f; geow[base+1] = 0.0f;
        return;
    }
    float c1 = rois[rr*4 + (isY ? 1 : 0)];
    float c2 = rois[rr*4 + (isY ? 3 : 2)];
    float lo = c1 * (1.0f/32.0f);
    float hi = c2 * (1.0f/32.0f);
    float sz = fmaxf(hi - lo, 1.0f);
    float g = ((float)ii + 0.5f) / 14.0f;
    float p = fminf(fmaxf(lo + g*sz, 0.0f), 15.0f);
    int p0 = (int)floorf(p);
    int p1 = min(p0 + 1, 15);
    float l = p - (float)p0;
    geoi[base] = p0; geoi[base+1] = p1;
    geow[base] = 0.5f * (1.0f - l); geow[base+1] = 0.5f * l;
}

// ---------------- ROI align v3 ----------------
__global__ void __launch_bounds__(256)
roi_align3_kernel(const float* __restrict__ feat,
                  const int* __restrict__ geoi, const float* __restrict__ geow,
                  u16* __restrict__ Ah) {
    __shared__ float ftile[16*256];
    __shared__ int   si[64*56];
    __shared__ float sw[64*56];
    int cg = blockIdx.x;
    int chunk = blockIdx.y;
    int tid = threadIdx.x;
    {
        const float4* src = (const float4*)(feat + (size_t)cg*16*256);
        float4* dst = (float4*)ftile;
        for (int i = tid; i < 1024; i += 256) dst[i] = src[i];
    }
    int gbase = chunk*64*56;
    for (int i = tid; i < 64*56; i += 256) {
        si[i] = geoi[gbase + i];
        sw[i] = geow[gbase + i];
    }
    __syncthreads();

    for (int rl = 0; rl < 64; rl++) {
        int rr = chunk*64 + rl;
        const int* gi = si + rl*56;
        const float* gw = sw + rl*56;
        for (int t = tid; t < 784; t += 256) {
            int cl = t / 49, p = t % 49;
            int py = p / 7, px = p % 7;
            const float* f = ftile + cl*256;
            float acc = 0.0f;
            #pragma unroll
            for (int a = 0; a < 4; a++) {
                const float* frow = f + gi[28 + py*4 + a]*16;
                float sv = 0.0f;
                #pragma unroll
                for (int bb = 0; bb < 4; bb++)
                    sv = fmaf(gw[px*4 + bb], frow[gi[px*4 + bb]], sv);
                acc = fmaf(gw[28 + py*4 + a], sv, acc);
            }
            __half h = __float2half_rn(acc);
            Ah[(size_t)rr*25088 + (size_t)(cg*16 + cl)*49 + p] = *(u16*)&h;
        }
    }
}

// ---------------- transpose + fp16 weights ----------------
__global__ void tsplit_kernel(const float* __restrict__ W,
                              u16* __restrict__ Th, int K, int N) {
    __shared__ float t[32][33];
    int n0 = blockIdx.x * 32, k0 = blockIdx.y * 32;
    int tx = threadIdx.x, ty = threadIdx.y;
    #pragma unroll
    for (int i = 0; i < 4; i++)
        t[ty + 8*i][tx] = W[(size_t)(k0 + ty + 8*i)*N + n0 + tx];
    __syncthreads();
    #pragma unroll
    for (int i = 0; i < 4; i++) {
        __half h = __float2half_rn(t[tx][ty + 8*i]);
        Th[(size_t)(n0 + ty + 8*i)*K + k0 + tx] = *(u16*)&h;
    }
}

// ---------------- single-pass fp16 tensor-core GEMM (fc path, fp16 partials) ----------------
__global__ void __launch_bounds__(256)
gemm_fp16_kernel(const u16* __restrict__ A, const u16* __restrict__ B,
                 u16* __restrict__ parth, int K, int stages) {
    __shared__ __align__(16) u16 sm[2][2][128*LDK];
    int tid = threadIdx.x;
    int wid = tid >> 5, lane = tid & 31;
    int wm = (wid & 1) * 64;
    int wn = (wid >> 1) * 32;
    int g = lane >> 2, tig = lane & 3;
    int r8 = lane & 7, q = lane >> 3;
    int bm = blockIdx.y * 128, bn = blockIdx.x * 128;
    int kbase = blockIdx.z * stages * 16;

    float acc[16][4];
    #pragma unroll
    for (int i = 0; i < 16; i++)
        #pragma unroll
        for (int j = 0; j < 4; j++) acc[i][j] = 0.0f;

    uint32_t smb = (uint32_t)__cvta_generic_to_shared(&sm[0][0][0]);
    const uint32_t MAT = 128*LDK*2;
    const uint32_t BUF = 2*MAT;
    uint32_t offA = (uint32_t)(((wm + (q & 1)*8 + r8)*LDK + (q >> 1)*8) * 2);
    uint32_t offB = (uint32_t)(((wn + (q >> 1)*8 + r8)*LDK + (q & 1)*8) * 2);

    auto load_stage = [&](int buf, int s) {
        int kpos0 = kbase + s * 16;
        #pragma unroll
        for (int l = 0; l < 2; l++) {
            int idx = l * 256 + tid;
            int pl = idx >> 8;
            int rr = (idx & 255) >> 1;
            int half = idx & 1;
            const u16* src = (pl ? B + (size_t)(bn + rr)*K : A + (size_t)(bm + rr)*K)
                             + kpos0 + half*8;
            uint32_t dst = (uint32_t)__cvta_generic_to_shared(&sm[buf][pl][rr*LDK + half*8]);
            cpasync16(dst, src);
        }
        asm volatile("cp.async.commit_group;\n");
    };

    load_stage(0, 0);

    for (int s = 0; s < stages; s++) {
        if (s + 1 < stages) {
            load_stage((s + 1) & 1, s + 1);
            asm volatile("cp.async.wait_group 1;\n");
        } else {
            asm volatile("cp.async.wait_group 0;\n");
        }
        __syncthreads();
        uint32_t base = smb + (uint32_t)(s & 1)*BUF;
        uint32_t aA = base + offA;
        uint32_t aB = base + MAT + offB;

        uint32_t bh[4][2], ah[4][4];
        #pragma unroll
        for (int p = 0; p < 2; p++)
            ldsm_x4(bh[2*p][0], bh[2*p][1], bh[2*p+1][0], bh[2*p+1][1], aB + p*16*LDK*2);
        #pragma unroll
        for (int mi = 0; mi < 4; mi++)
            ldsm_x4(ah[mi][0], ah[mi][1], ah[mi][2], ah[mi][3], aA + mi*16*LDK*2);

        #pragma unroll
        for (int mi = 0; mi < 4; mi++)
            #pragma unroll
            for (int ni = 0; ni < 4; ni++) {
                float* d = acc[mi*4 + ni];
                mma16816_f32(d[0], d[1], d[2], d[3],
                             ah[mi][0], ah[mi][1], ah[mi][2], ah[mi][3], bh[ni][0], bh[ni][1]);
            }
        __syncthreads();
    }

    // fp16 partials: one half2 store per column pair (halves partial HBM traffic)
    u16* cbase = parth + ((size_t)blockIdx.z << 20);
    #pragma unroll
    for (int mi = 0; mi < 4; mi++) {
        #pragma unroll
        for (int ni = 0; ni < 4; ni++) {
            int row = bm + wm + mi*16 + g;
            int col = bn + wn + ni*8 + 2*tig;
            float* d = acc[mi*4 + ni];
            *(__half2*)&cbase[(size_t)row*1024 + col]     = __floats2half2_rn(d[0], d[1]);
            *(__half2*)&cbase[(size_t)(row+8)*1024 + col] = __floats2half2_rn(d[2], d[3]);
        }
    }
}

// reduce fc1 fp16 partials -> relu -> fp16 h1 (z=16)
__global__ void reduce1_kernel(const u16* __restrict__ parth,
                               const float* __restrict__ bias,
                               u16* __restrict__ Hh) {
    size_t idx = (size_t)blockIdx.x * 256 + threadIdx.x;
    int n = (int)(idx & 1023);
    float s = bias[n];
    #pragma unroll
    for (int i = 0; i < 16; i++) {
        u16 v = parth[((size_t)i << 20) + idx];
        s += __half2float(*(__half*)&v);
    }
    s = fmaxf(s, 0.0f);
    __half h = __float2half_rn(s);
    Hh[idx] = *(u16*)&h;
}

// reduce fc2 fp16 partials -> relu -> f32 h2 (z=4)
__global__ void reduce2_kernel(const u16* __restrict__ parth,
                               const float* __restrict__ bias,
                               float* __restrict__ H) {
    size_t idx = (size_t)blockIdx.x * 256 + threadIdx.x;
    int n = (int)(idx & 1023);
    float s = bias[n];
    #pragma unroll
    for (int i = 0; i < 4; i++) {
        u16 v = parth[((size_t)i << 20) + idx];
        s += __half2float(*(__half*)&v);
    }
    H[idx] = fmaxf(s, 0.0f);
}

// ---------------- cls + bbox heads: block per roi ----------------
__global__ void __launch_bounds__(256)
fc_small2_kernel(const float* __restrict__ h,
                 const float* __restrict__ clsw, const float* __restrict__ clsb,
                 const float* __restrict__ bbw, const float* __restrict__ bbb,
                 float* __restrict__ logits, float* __restrict__ breg) {
    __shared__ float hs[1024];
    int r = blockIdx.x;
    int tid = threadIdx.x;
    const float* hp = h + (size_t)r*1024;
    for (int i = tid; i < 1024; i += 256) hs[i] = hp[i];
    __syncthreads();
    if (tid < 240) {
        int j = tid >> 3, part = tid & 7;
        float acc = 0.0f;
        if (j < 6) {
            for (int k = part; k < 1024; k += 8)
                acc = fmaf(hs[k], clsw[k*6 + j], acc);
        } else {
            int q = j - 6;
            for (int k = part; k < 1024; k += 8)
                acc = fmaf(hs[k], bbw[k*24 + q], acc);
        }
        #pragma unroll
        for (int off = 4; off; off >>= 1)
            acc += __shfl_down_sync(0xffffffff, acc, off);
        if (part == 0) {
            if (j < 6) logits[r*6 + j] = acc + clsb[j];
            else       breg[r*24 + (j-6)] = acc + bbb[j-6];
        }
    }
}

// ---------------- final ----------------
__global__ void final_kernel(const float* __restrict__ rois,
                             const float* __restrict__ logits,
                             const float* __restrict__ breg,
                             float* __restrict__ out) {
    int r = blockIdx.x * 128 + threadIdx.x;
    if (r >= TOPN) return;
    float l[6];
    float m = -INFINITY;
    #pragma unroll
    for (int i = 0; i < 6; i++) { l[i] = logits[r*6 + i]; m = fmaxf(m, l[i]); }
    float ssum = 0.0f;
    #pragma unroll
    for (int i = 0; i < 6; i++) { l[i] = expf(l[i] - m); ssum += l[i]; }
    float inv = 1.0f / ssum;

    float x1 = rois[r*4+0], y1 = rois[r*4+1], x2 = rois[r*4+2], y2 = rois[r*4+3];
    float W = x2 - x1, H = y2 - y1;
    float cx = x1 + 0.5f*W, cy = y1 + 0.5f*H;
    #pragma unroll
    for (int c = 1; c < 6; c++) {
        float dx = breg[r*24 + c*4+0] / 10.0f;
        float dy = breg[r*24 + c*4+1] / 10.0f;
        float dw = fminf(breg[r*24 + c*4+2] / 5.0f, BBOX_CLAMP);
        float dh = fminf(breg[r*24 + c*4+3] / 5.0f, BBOX_CLAMP);
        float pcx = dx*W + cx, pcy = dy*H + cy;
        float pw = expf(dw)*W, ph = expf(dh)*H;
        float bx1 = fminf(fmaxf(pcx - 0.5f*pw, 0.0f), 512.0f);
        float by1 = fminf(fmaxf(pcy - 0.5f*ph, 0.0f), 512.0f);
        float bx2 = fminf(fmaxf(pcx + 0.5f*pw, 0.0f), 512.0f);
        float by2 = fminf(fmaxf(pcy + 0.5f*ph, 0.0f), 512.0f);
        int o = r*25 + (c-1)*5;
        out[o+0] = bx1; out[o+1] = by1; out[o+2] = bx2; out[o+3] = by2;
        out[o+4] = l[c] * inv;
    }
}

// ---------------- launcher ----------------
extern "C" void kernel_launch(void* const* d_in, const int* in_sizes, int n_in,
                              void* d_out, int out_size) {
    const float* images     = (const float*)d_in[0];
    const float* c0_w       = (const float*)d_in[1];
    const float* c0_b       = (const float*)d_in[2];
    const float* c1_w       = (const float*)d_in[3];
    const float* c1_b       = (const float*)d_in[4];
    const float* c2_w       = (const float*)d_in[5];
    const float* c2_b       = (const float*)d_in[6];
    const float* c3_w       = (const float*)d_in[7];
    const float* c3_b       = (const float*)d_in[8];
    const float* rpn_conv_w = (const float*)d_in[9];
    const float* rpn_conv_b = (const float*)d_in[10];
    const float* rpn_cls_w  = (const float*)d_in[11];
    const float* rpn_cls_b  = (const float*)d_in[12];
    const float* rpn_bbox_w = (const float*)d_in[13];
    const float* rpn_bbox_b = (const float*)d_in[14];
    const float* fc1_w      = (const float*)d_in[15];
    const float* fc1_b      = (const float*)d_in[16];
    const float* fc2_w      = (const float*)d_in[17];
    const float* fc2_b      = (const float*)d_in[18];
    const float* cls_w      = (const float*)d_in[19];
    const float* cls_b      = (const float*)d_in[20];
    const float* bbox_w     = (const float*)d_in[21];
    const float* bbox_b     = (const float*)d_in[22];
    float* out = (float*)d_out;

    float *p_c0, *p_pool, *p_c1, *p_c2, *p_feat, *p_rpn, *p_obj, *p_bd;
    float *p_props, *p_scores, *p_rois, *p_part, *p_h2, *p_logits, *p_breg, *p_geow;
    int *p_topidx, *p_geoi;
    u16 *p_Ah, *p_B1h, *p_B2h, *p_h1h, *p_cAh, *p_cAl, *p_cBh, *p_cBl;
    cudaGetSymbolAddress((void**)&p_c0, g_c0);
    cudaGetSymbolAddress((void**)&p_pool, g_pool);
    cudaGetSymbolAddress((void**)&p_c1, g_c1);
    cudaGetSymbolAddress((void**)&p_c2, g_c2);
    cudaGetSymbolAddress((void**)&p_feat, g_feat);
    cudaGetSymbolAddress((void**)&p_rpn, g_rpn);
    cudaGetSymbolAddress((void**)&p_obj, g_obj);
    cudaGetSymbolAddress((void**)&p_bd, g_bd);
    cudaGetSymbolAddress((void**)&p_props, g_props);
    cudaGetSymbolAddress((void**)&p_scores, g_scores);
    cudaGetSymbolAddress((void**)&p_topidx, g_topidx);
    cudaGetSymbolAddress((void**)&p_rois, g_rois);
    cudaGetSymbolAddress((void**)&p_geoi, g_geoi);
    cudaGetSymbolAddress((void**)&p_geow, g_geow);
    cudaGetSymbolAddress((void**)&p_cAh, g_cAh);
    cudaGetSymbolAddress((void**)&p_cAl, g_cAl);
    cudaGetSymbolAddress((void**)&p_cBh, g_cBh);
    cudaGetSymbolAddress((void**)&p_cBl, g_cBl);
    cudaGetSymbolAddress((void**)&p_Ah, g_Ah);
    cudaGetSymbolAddress((void**)&p_B1h, g_B1h);
    cudaGetSymbolAddress((void**)&p_B2h, g_B2h);
    cudaGetSymbolAddress((void**)&p_h1h, g_h1h);
    cudaGetSymbolAddress((void**)&p_part, g_part);
    cudaGetSymbolAddress((void**)&p_h2, g_h2);
    cudaGetSymbolAddress((void**)&p_logits, g_logits);
    cudaGetSymbolAddress((void**)&p_breg, g_breg);
    u16* p_parth = (u16*)p_part;   // fc path reuses scratch as fp16 partials

    // second stream for independent fc-weight transpose (round-13 config)
    static cudaStream_t s2 = 0;
    static cudaEvent_t evF = 0, evJ = 0;
    if (!s2) {
        cudaStreamCreateWithFlags(&s2, cudaStreamNonBlocking);
        cudaEventCreateWithFlags(&evF, cudaEventDisableTiming);
        cudaEventCreateWithFlags(&evJ, cudaEventDisableTiming);
    }
    cudaEventRecord(evF, 0);
    cudaStreamWaitEvent(s2, evF, 0);
    tsplit_kernel<<<dim3(1024/32, 25088/32), dim3(32,8), 0, s2>>>(fc1_w, p_B1h, 25088, 1024);
    tsplit_kernel<<<dim3(1024/32, 1024/32),  dim3(32,8), 0, s2>>>(fc2_w, p_B2h, 1024, 1024);
    cudaEventRecord(evJ, s2);

    // backbone: conv0 + pool, then implicit-GEMM convs (wsplits inline)
    conv0v2_kernel<<<dim3(8,16,16), dim3(8,16)>>>(images, c0_w, c0_b, p_c0);
    maxpool_kernel<<<(64*128*128 + 255)/256, 256>>>(p_c0, p_pool);

    // c1
    im2col_kernel<<<(4096*576 + 255)/256, 256>>>(p_pool, p_cAh, p_cAl, 64, 128, 64, 2, 4096*576);
    wsplit_kernel<<<(128*576 + 255)/256, 256>>>(c1_w, p_cBh, p_cBl, 128*576);
    gemm_split3_kernel<<<dim3(1,32,9), 256>>>(p_cAh, p_cAl, p_cBh, p_cBl, p_part, 576, 4, 128);
    creduceT_kernel<<<(4096*128 + 255)/256, 256>>>(p_part, c1_b, p_c1, 4096, 128, 9);

    // c2
    im2col_kernel<<<(1024*1152 + 255)/256, 256>>>(p_c1, p_cAh, p_cAl, 128, 64, 32, 2, 1024*1152);
    wsplit_kernel<<<(256*1152 + 255)/256, 256>>>(c2_w, p_cBh, p_cBl, 256*1152);
    gemm_split3_kernel<<<dim3(2,8,12), 256>>>(p_cAh, p_cAl, p_cBh, p_cBl, p_part, 1152, 6, 256);
    creduceT_kernel<<<(1024*256 + 255)/256, 256>>>(p_part, c2_b, p_c2, 1024, 256, 12);

    // c3
    im2col_kernel<<<(256*2304 + 255)/256, 256>>>(p_c2, p_cAh, p_cAl, 256, 32, 16, 2, 256*2304);
    wsplit_kernel<<<(512*2304 + 255)/256, 256>>>(c3_w, p_cBh, p_cBl, 512*2304);
    gemm_split3_kernel<<<dim3(4,2,18), 256>>>(p_cAh, p_cAl, p_cBh, p_cBl, p_part, 2304, 8, 512);
    creduceT_kernel<<<(256*512 + 255)/256, 256>>>(p_part, c3_b, p_feat, 256, 512, 18);

    // rpn conv
    im2col_kernel<<<(256*4608 + 255)/256, 256>>>(p_feat, p_cAh, p_cAl, 512, 16, 16, 1, 256*4608);
    wsplit_kernel<<<(512*4608 + 255)/256, 256>>>(rpn_conv_w, p_cBh, p_cBl, 512*4608);
    gemm_split3_kernel<<<dim3(4,2,24), 256>>>(p_cAh, p_cAl, p_cBh, p_cBl, p_part, 4608, 12, 512);
    creduceT_kernel<<<(256*512 + 255)/256, 256>>>(p_part, rpn_conv_b, p_rpn, 256, 512, 24);

    // RPN heads
    rpnheads_kernel<<<45, 256>>>(p_rpn, rpn_cls_w, rpn_cls_b, rpn_bbox_w, rpn_bbox_b, p_obj, p_bd);

    // proposals (separate kernels — proven config)
    rpn_decode_kernel<<<9, 256>>>(p_obj, p_bd, p_props, p_scores);
    topk_kernel<<<1, 1024>>>(p_scores, p_topidx);
    gather_rois_kernel<<<4, 256>>>(p_props, p_topidx, p_rois);
    roigeo_kernel<<<(1024*28 + 255)/256, 256>>>(p_rois, p_geoi, p_geow);

    // roi align -> fp16 A
    roi_align3_kernel<<<dim3(32,16), 256>>>(p_feat, p_geoi, p_geow, p_Ah);

    // join fc weights
    cudaStreamWaitEvent(0, evJ, 0);

    // fc1: K=25088, z=16 -> stages 98 (fp16 partials)
    gemm_fp16_kernel<<<dim3(8,8,16), 256>>>(p_Ah, p_B1h, p_parth, 25088, 98);
    reduce1_kernel<<<(1024*1024)/256, 256>>>(p_parth, fc1_b, p_h1h);

    // fc2: K=1024, z=4 -> stages 16 (fp16 partials)
    gemm_fp16_kernel<<<dim3(8,8,4), 256>>>(p_h1h, p_B2h, p_parth, 1024, 16);
    reduce2_kernel<<<(1024*1024)/256, 256>>>(p_parth, fc2_b, p_h2);

    fc_small2_kernel<<<TOPN, 256>>>(p_h2, cls_w, cls_b, bbox_w, bbox_b, p_logits, p_breg);
    final_kernel<<<(TOPN + 127)/128, 128>>>(p_rois, p_logits, p_breg, out);
}